// round 2
// baseline (speedup 1.0000x reference)
#include <cuda_runtime.h>
#include <math.h>

// Problem dims (fixed by setup_inputs)
#define Bb 8
#define Ss 4096
#define Dd 512
#define Hh 512
#define GH 1024
#define Mm (Bb * Ss)          // 32768 rows
#define NCHUNK 64             // chunks along S for the parallel scan
#define CLEN (Ss / NCHUNK)    // 64 steps per chunk
#define NCH (Bb * Hh)         // 4096 independent recurrence channels

// Scratch (device globals: allocation-free per harness rules)
__device__ float g_gh[(size_t)Mm * GH];     // GEMM output gate/hidden; gate slot reused for cumprod
__device__ float g_out0[(size_t)Mm * Hh];   // layer-0 output
__device__ float g_carryP[NCHUNK * NCH];
__device__ float g_carryH[NCHUNK * NCH];
__device__ float g_entry[NCHUNK * NCH];

// ---------------------------------------------------------------------------
// SGEMM with bias: C[m,n] = sum_k A[m,k]*W[n,k] + bias[n]
// A: [Mm, K] row-major, W: [GH, K] row-major, C: [Mm, GH]
// Block tile 128x128, BK=8, 256 threads, 8x8 per-thread microtile.
// ---------------------------------------------------------------------------
__global__ __launch_bounds__(256) void sgemm_bias_kernel(
    const float* __restrict__ A, const float* __restrict__ W,
    const float* __restrict__ bias, float* __restrict__ C, int K)
{
    __shared__ float As[8][128];
    __shared__ float Ws[8][128];

    const int tid = threadIdx.x;
    const int ty = tid >> 4;        // 0..15
    const int tx = tid & 15;        // 0..15
    const int rowBase = blockIdx.y * 128;
    const int colBase = blockIdx.x * 128;

    const int lr = tid >> 1;        // 0..127 tile row for loads
    const int lc = (tid & 1) * 4;   // 0 or 4

    const float* Aptr = A + (size_t)(rowBase + lr) * K + lc;
    const float* Wptr = W + (size_t)(colBase + lr) * K + lc;

    float acc[8][8];
#pragma unroll
    for (int i = 0; i < 8; i++)
#pragma unroll
        for (int j = 0; j < 8; j++) acc[i][j] = 0.f;

    for (int k0 = 0; k0 < K; k0 += 8) {
        float4 a = *(const float4*)(Aptr + k0);
        float4 w = *(const float4*)(Wptr + k0);
        __syncthreads();
        As[lc + 0][lr] = a.x; As[lc + 1][lr] = a.y;
        As[lc + 2][lr] = a.z; As[lc + 3][lr] = a.w;
        Ws[lc + 0][lr] = w.x; Ws[lc + 1][lr] = w.y;
        Ws[lc + 2][lr] = w.z; Ws[lc + 3][lr] = w.w;
        __syncthreads();
#pragma unroll
        for (int k = 0; k < 8; k++) {
            float ra[8], rb[8];
#pragma unroll
            for (int i = 0; i < 8; i++) ra[i] = As[k][ty * 8 + i];
#pragma unroll
            for (int j = 0; j < 8; j++) rb[j] = Ws[k][tx * 8 + j];
#pragma unroll
            for (int i = 0; i < 8; i++)
#pragma unroll
                for (int j = 0; j < 8; j++)
                    acc[i][j] = fmaf(ra[i], rb[j], acc[i][j]);
        }
    }

#pragma unroll
    for (int i = 0; i < 8; i++) {
        const int m = rowBase + ty * 8 + i;
        float* crow = C + (size_t)m * GH + colBase + tx * 8;
#pragma unroll
        for (int j = 0; j < 8; j++)
            crow[j] = acc[i][j] + bias[colBase + tx * 8 + j];
    }
}

// ---------------------------------------------------------------------------
// Scan pass 1: per (channel, chunk) local scan with h_in = 0.
// Reads gate/hidden from gh, writes local h to `localh`, writes inclusive
// cumulative product P into gh's gate slot (overwrite after read).
// g = h + 512*(b + 8*k) -> coalesced over h.
// ---------------------------------------------------------------------------
__global__ __launch_bounds__(256) void scan_local_kernel(
    float* __restrict__ gh, float* __restrict__ localh)
{
    const int g = blockIdx.x * blockDim.x + threadIdx.x;  // 0 .. NCHUNK*NCH-1
    const int h = g & (Hh - 1);
    const int rest = g >> 9;
    const int b = rest & (Bb - 1);
    const int k = rest >> 3;

    float P = 1.0f, hl = 0.0f;
    size_t base = ((size_t)(b * Ss + k * CLEN)) * GH + h;
    size_t obase = ((size_t)(b * Ss + k * CLEN)) * Hh + h;

    for (int i = 0; i < CLEN; i++) {
        float gate = gh[base];
        float hid  = gh[base + Hh];
        float z = 1.0f / (1.0f + __expf(-gate));           // sigmoid(gate)
        float c = 1.0f / (1.0f + __expf(gate));            // sigmoid(-gate)
        float gg = (hid >= 0.0f) ? (hid + 0.5f)
                                 : 1.0f / (1.0f + __expf(-hid));
        float v = z * gg;
        hl = fmaf(c, hl, v);
        P *= c;
        localh[obase] = hl;
        gh[base] = P;              // stash cumprod for the fix-up pass
        base += GH;
        obase += Hh;
    }

    const int ch = b * Hh + h;
    g_carryP[k * NCH + ch] = P;
    g_carryH[k * NCH + ch] = hl;
}

// ---------------------------------------------------------------------------
// Scan pass 2: scan the per-chunk carries sequentially per channel (64 steps),
// producing the chunk-entry h. Also writes next_hidden (= final h) directly.
// ---------------------------------------------------------------------------
__global__ __launch_bounds__(256) void scan_carry_kernel(float* __restrict__ nh_out)
{
    const int ch = blockIdx.x * blockDim.x + threadIdx.x;  // 0..4095
    float hcur = 0.5f;                                     // h0
#pragma unroll 4
    for (int k = 0; k < NCHUNK; k++) {
        g_entry[k * NCH + ch] = hcur;
        hcur = fmaf(g_carryP[k * NCH + ch], hcur, g_carryH[k * NCH + ch]);
    }
    nh_out[ch] = hcur;
}

// ---------------------------------------------------------------------------
// Scan pass 3: out[t] = local[t] + cumprod[t] * h_entry[chunk]. float4 over h.
// ---------------------------------------------------------------------------
__global__ __launch_bounds__(256) void scan_fix_kernel(
    const float* __restrict__ cumP, float* __restrict__ outbuf)
{
    const int g = blockIdx.x * blockDim.x + threadIdx.x;   // Mm*Hh/4 threads
    const int h4 = (g & (Hh / 4 - 1)) * 4;
    const int n = g >> 7;            // b*Ss + s   (Hh/4 == 128)
    const int s = n & (Ss - 1);
    const int b = n >> 12;
    const int k = s >> 6;            // s / CLEN

    float4 P  = *(const float4*)(cumP + (size_t)n * GH + h4);
    float4 hl = *(const float4*)(outbuf + (size_t)n * Hh + h4);
    float4 e  = *(const float4*)(g_entry + k * NCH + b * Hh + h4);
    float4 r;
    r.x = fmaf(P.x, e.x, hl.x);
    r.y = fmaf(P.y, e.y, hl.y);
    r.z = fmaf(P.z, e.z, hl.z);
    r.w = fmaf(P.w, e.w, hl.w);
    *(float4*)(outbuf + (size_t)n * Hh + h4) = r;
}

// ---------------------------------------------------------------------------
extern "C" void kernel_launch(void* const* d_in, const int* in_sizes, int n_in,
                              void* d_out, int out_size)
{
    const float* x  = (const float*)d_in[0];
    const float* w0 = (const float*)d_in[1];
    const float* b0 = (const float*)d_in[2];
    const float* w1 = (const float*)d_in[3];
    const float* b1 = (const float*)d_in[4];
    float* out = (float*)d_out;

    float* gh;    cudaGetSymbolAddress((void**)&gh,    g_gh);
    float* out0;  cudaGetSymbolAddress((void**)&out0,  g_out0);

    float* nh0 = out + (size_t)Mm * Hh;            // next_hidden layer 0
    float* nh1 = nh0 + (size_t)Bb * Hh;            // next_hidden layer 1

    dim3 ggrid(GH / 128, Mm / 128);                // (8, 256)
    const int scan1_blocks = (NCHUNK * NCH) / 256; // 1024
    const int fix_blocks = (Mm * Hh / 4) / 256;    // 16384

    // ---- Layer 0 ----
    sgemm_bias_kernel<<<ggrid, 256>>>(x, w0, b0, gh, Dd);
    scan_local_kernel<<<scan1_blocks, 256>>>(gh, out0);
    scan_carry_kernel<<<NCH / 256, 256>>>(nh0);
    scan_fix_kernel<<<fix_blocks, 256>>>(gh, out0);

    // ---- Layer 1 ----
    sgemm_bias_kernel<<<ggrid, 256>>>(out0, w1, b1, gh, Hh);
    scan_local_kernel<<<scan1_blocks, 256>>>(gh, out);
    scan_carry_kernel<<<NCH / 256, 256>>>(nh1);
    scan_fix_kernel<<<fix_blocks, 256>>>(gh, out);
}

// round 6
// speedup vs baseline: 2.7997x; 2.7997x over previous
#include <cuda_runtime.h>
#include <cuda_bf16.h>
#include <cstdint>
#include <math.h>

// Problem dims (fixed by setup_inputs)
#define Bb 8
#define Ss 4096
#define Dd 512
#define Hh 512
#define GH 1024
#define Mm (Bb * Ss)          // 32768 rows
#define KP 1536               // split-extended K: [hi | lo | hi] x [hi | hi | lo]
#define NCHUNK 64
#define CLEN (Ss / NCHUNK)
#define NCH (Bb * Hh)

// Scratch (device globals: allocation-free per harness rules)
__device__ float g_gh[(size_t)Mm * GH];
__device__ float g_out0[(size_t)Mm * Hh];
__device__ __nv_bfloat16 g_Ax[(size_t)Mm * KP];   // layer-0 A operand (split)
__device__ __nv_bfloat16 g_A1[(size_t)Mm * KP];   // layer-1 A operand (split)
__device__ __nv_bfloat16 g_Wb0[(size_t)GH * KP];
__device__ __nv_bfloat16 g_Wb1[(size_t)GH * KP];
__device__ float g_carryP[NCHUNK * NCH];
__device__ float g_carryH[NCHUNK * NCH];
__device__ float g_entry[NCHUNK * NCH];

// ===========================================================================
// Helpers
// ===========================================================================
__device__ __forceinline__ uint32_t smem_u32(const void* p) {
    uint32_t a;
    asm("{ .reg .u64 t; cvta.to.shared.u64 t, %1; cvt.u32.u64 %0, t; }" : "=r"(a) : "l"(p));
    return a;
}

#define CP_ASYNC16(smaddr, gptr) \
    asm volatile("cp.async.cg.shared.global [%0], [%1], 16;" :: "r"(smaddr), "l"(gptr) : "memory")
#define CP_COMMIT  asm volatile("cp.async.commit_group;" ::: "memory")
#define CP_WAIT0   asm volatile("cp.async.wait_group 0;" ::: "memory")
#define CP_WAIT1   asm volatile("cp.async.wait_group 1;" ::: "memory")

#define LDSM_X4(r0, r1, r2, r3, addr) \
    asm volatile("ldmatrix.sync.aligned.m8n8.x4.shared.b16 {%0,%1,%2,%3}, [%4];" \
        : "=r"(r0), "=r"(r1), "=r"(r2), "=r"(r3) : "r"(addr))

#define MMA16816(c, a, b) \
    asm volatile("mma.sync.aligned.m16n8k16.row.col.f32.bf16.bf16.f32 " \
        "{%0,%1,%2,%3}, {%4,%5,%6,%7}, {%8,%9}, {%0,%1,%2,%3};" \
        : "+f"((c)[0]), "+f"((c)[1]), "+f"((c)[2]), "+f"((c)[3]) \
        : "r"((a)[0]), "r"((a)[1]), "r"((a)[2]), "r"((a)[3]), "r"((b)[0]), "r"((b)[1]))

// Split a float4 into hi/lo bf16 pairs (packed as 2x u32 each)
__device__ __forceinline__ void split4(float4 f, uint32_t& h01, uint32_t& h23,
                                       uint32_t& l01, uint32_t& l23) {
    __nv_bfloat162 h0, h1, l0, l1;
    h0.x = __float2bfloat16_rn(f.x); h0.y = __float2bfloat16_rn(f.y);
    h1.x = __float2bfloat16_rn(f.z); h1.y = __float2bfloat16_rn(f.w);
    l0.x = __float2bfloat16_rn(f.x - __bfloat162float(h0.x));
    l0.y = __float2bfloat16_rn(f.y - __bfloat162float(h0.y));
    l1.x = __float2bfloat16_rn(f.z - __bfloat162float(h1.x));
    l1.y = __float2bfloat16_rn(f.w - __bfloat162float(h1.y));
    h01 = *reinterpret_cast<uint32_t*>(&h0);
    h23 = *reinterpret_cast<uint32_t*>(&h1);
    l01 = *reinterpret_cast<uint32_t*>(&l0);
    l23 = *reinterpret_cast<uint32_t*>(&l1);
}

// ===========================================================================
// Conversion kernels: fp32 [rows][512] -> bf16 [rows][1536]
// A-mode: [hi | lo | hi];  B-mode (weights): [hi | hi | lo]
// ===========================================================================
__global__ __launch_bounds__(256) void conv_a_kernel(
    const float* __restrict__ in, __nv_bfloat16* __restrict__ out)
{
    const int g = blockIdx.x * 256 + threadIdx.x;
    const int row = g >> 7;            // 128 quads per 512-wide row
    const int k4 = (g & 127) * 4;
    float4 f = *(const float4*)(in + (size_t)row * 512 + k4);
    uint32_t h01, h23, l01, l23;
    split4(f, h01, h23, l01, l23);
    __nv_bfloat16* orow = out + (size_t)row * KP;
    *(uint2*)(orow + k4)        = make_uint2(h01, h23);
    *(uint2*)(orow + 512 + k4)  = make_uint2(l01, l23);
    *(uint2*)(orow + 1024 + k4) = make_uint2(h01, h23);
}

__global__ __launch_bounds__(256) void conv_b_kernel(
    const float* __restrict__ in, __nv_bfloat16* __restrict__ out)
{
    const int g = blockIdx.x * 256 + threadIdx.x;
    const int row = g >> 7;
    const int k4 = (g & 127) * 4;
    float4 f = *(const float4*)(in + (size_t)row * 512 + k4);
    uint32_t h01, h23, l01, l23;
    split4(f, h01, h23, l01, l23);
    __nv_bfloat16* orow = out + (size_t)row * KP;
    *(uint2*)(orow + k4)        = make_uint2(h01, h23);
    *(uint2*)(orow + 512 + k4)  = make_uint2(h01, h23);
    *(uint2*)(orow + 1024 + k4) = make_uint2(l01, l23);
}

// ===========================================================================
// HMMA GEMM with bias: C[m,n] = sum_k' A[m,k']*B[n,k'] + bias[n]
// A: [Mm][KP] bf16, B: [GH][KP] bf16 (row-major over n, K contiguous)
// CTA tile 128x128, BK=64, 256 threads, double-buffered cp.async.
// ===========================================================================
#define BM 128
#define BN 128
#define BK 64
#define NKT (KP / BK)          // 24
#define GEMM_SMEM 65536        // 2 stages x (16KB A + 16KB B)

__global__ __launch_bounds__(256, 2) void hmma_gemm_bias(
    const __nv_bfloat16* __restrict__ A, const __nv_bfloat16* __restrict__ Bw,
    const float* __restrict__ bias, float* __restrict__ C)
{
    extern __shared__ char sm[];
    const uint32_t sA = smem_u32(sm);          // [2][16384] bytes
    const uint32_t sB = sA + 32768;
    const int tid = threadIdx.x;
    const int lane = tid & 31;
    const int wid = tid >> 5;
    const int rowBase = blockIdx.y * BM;
    const int colBase = blockIdx.x * BN;
    const int wm = (wid & 3) * 32;             // warp M offset
    const int wn = (wid >> 2) * 64;            // warp N offset

    float acc[2][8][4];
#pragma unroll
    for (int mf = 0; mf < 2; mf++)
#pragma unroll
        for (int nf = 0; nf < 8; nf++)
#pragma unroll
            for (int j = 0; j < 4; j++) acc[mf][nf][j] = 0.f;

    // stage loader: 128 rows x 128 bytes for A and B each (1024 chunks of 16B)
    auto loadStage = [&](int kt, int s) {
#pragma unroll
        for (int i = 0; i < 4; i++) {
            const int id = tid + i * 256;
            const int r = id >> 3, c = id & 7;
            uint32_t off = (uint32_t)(r * 128 + c * 16);
            off ^= (off >> 3) & 0x70;
            CP_ASYNC16(sA + s * 16384 + off,
                       A + (size_t)(rowBase + r) * KP + kt * BK + c * 8);
        }
#pragma unroll
        for (int i = 0; i < 4; i++) {
            const int id = tid + i * 256;
            const int r = id >> 3, c = id & 7;
            uint32_t off = (uint32_t)(r * 128 + c * 16);
            off ^= (off >> 3) & 0x70;
            CP_ASYNC16(sB + s * 16384 + off,
                       Bw + (size_t)(colBase + r) * KP + kt * BK + c * 8);
        }
        CP_COMMIT;
    };

    loadStage(0, 0);

    for (int kt = 0; kt < NKT; kt++) {
        const int s = kt & 1;
        if (kt + 1 < NKT) {
            loadStage(kt + 1, s ^ 1);
            CP_WAIT1;
        } else {
            CP_WAIT0;
        }
        __syncthreads();

        const uint32_t aB = sA + s * 16384;
        const uint32_t bB = sB + s * 16384;
#pragma unroll
        for (int ks = 0; ks < 4; ks++) {
            uint32_t af[2][4];
#pragma unroll
            for (int mf = 0; mf < 2; mf++) {
                const int r = wm + mf * 16 + (lane & 15);
                const int kb = ks * 32 + (lane >> 4) * 16;
                uint32_t off = (uint32_t)(r * 128 + kb);
                off ^= (off >> 3) & 0x70;
                LDSM_X4(af[mf][0], af[mf][1], af[mf][2], af[mf][3], aB + off);
            }
            uint32_t bf[8][2];
#pragma unroll
            for (int n2 = 0; n2 < 4; n2++) {
                const int r = wn + n2 * 16 + (lane & 7) + ((lane >> 4) & 1) * 8;
                const int kb = ks * 32 + ((lane >> 3) & 1) * 16;
                uint32_t off = (uint32_t)(r * 128 + kb);
                off ^= (off >> 3) & 0x70;
                LDSM_X4(bf[2 * n2][0], bf[2 * n2][1], bf[2 * n2 + 1][0], bf[2 * n2 + 1][1],
                        bB + off);
            }
#pragma unroll
            for (int mf = 0; mf < 2; mf++)
#pragma unroll
                for (int nf = 0; nf < 8; nf++)
                    MMA16816(acc[mf][nf], af[mf], bf[nf]);
        }
        __syncthreads();
    }

    // Epilogue: C = acc + bias
#pragma unroll
    for (int mf = 0; mf < 2; mf++) {
        const int r0 = rowBase + wm + mf * 16 + (lane >> 2);
#pragma unroll
        for (int nf = 0; nf < 8; nf++) {
            const int col = colBase + wn + nf * 8 + 2 * (lane & 3);
            const float bx = __ldg(bias + col);
            const float by = __ldg(bias + col + 1);
            float2 v0, v1;
            v0.x = acc[mf][nf][0] + bx; v0.y = acc[mf][nf][1] + by;
            v1.x = acc[mf][nf][2] + bx; v1.y = acc[mf][nf][3] + by;
            *(float2*)(C + (size_t)r0 * GH + col) = v0;
            *(float2*)(C + (size_t)(r0 + 8) * GH + col) = v1;
        }
    }
}

// ===========================================================================
// Scan kernels (validated in Round 1/2)
// ===========================================================================
__global__ __launch_bounds__(256) void scan_local_kernel(
    float* __restrict__ gh, float* __restrict__ localh)
{
    const int g = blockIdx.x * blockDim.x + threadIdx.x;
    const int h = g & (Hh - 1);
    const int rest = g >> 9;
    const int b = rest & (Bb - 1);
    const int k = rest >> 3;

    float P = 1.0f, hl = 0.0f;
    size_t base = ((size_t)(b * Ss + k * CLEN)) * GH + h;
    size_t obase = ((size_t)(b * Ss + k * CLEN)) * Hh + h;

    for (int i = 0; i < CLEN; i++) {
        float gate = gh[base];
        float hid  = gh[base + Hh];
        float z = 1.0f / (1.0f + __expf(-gate));
        float cc = 1.0f / (1.0f + __expf(gate));
        float gg = (hid >= 0.0f) ? (hid + 0.5f) : 1.0f / (1.0f + __expf(-hid));
        float v = z * gg;
        hl = fmaf(cc, hl, v);
        P *= cc;
        localh[obase] = hl;
        gh[base] = P;
        base += GH;
        obase += Hh;
    }
    const int ch = b * Hh + h;
    g_carryP[k * NCH + ch] = P;
    g_carryH[k * NCH + ch] = hl;
}

__global__ __launch_bounds__(256) void scan_carry_kernel(float* __restrict__ nh_out)
{
    const int ch = blockIdx.x * blockDim.x + threadIdx.x;
    float hcur = 0.5f;
#pragma unroll 4
    for (int k = 0; k < NCHUNK; k++) {
        g_entry[k * NCH + ch] = hcur;
        hcur = fmaf(g_carryP[k * NCH + ch], hcur, g_carryH[k * NCH + ch]);
    }
    nh_out[ch] = hcur;
}

// Layer-1 fix-up: write final fp32 h in place
__global__ __launch_bounds__(256) void scan_fix_kernel(
    const float* __restrict__ cumP, float* __restrict__ outbuf)
{
    const int g = blockIdx.x * blockDim.x + threadIdx.x;
    const int h4 = (g & (Hh / 4 - 1)) * 4;
    const int n = g >> 7;
    const int s = n & (Ss - 1);
    const int b = n >> 12;
    const int k = s >> 6;

    float4 P  = *(const float4*)(cumP + (size_t)n * GH + h4);
    float4 hl = *(const float4*)(outbuf + (size_t)n * Hh + h4);
    float4 e  = *(const float4*)(g_entry + k * NCH + b * Hh + h4);
    float4 r;
    r.x = fmaf(P.x, e.x, hl.x);
    r.y = fmaf(P.y, e.y, hl.y);
    r.z = fmaf(P.z, e.z, hl.z);
    r.w = fmaf(P.w, e.w, hl.w);
    *(float4*)(outbuf + (size_t)n * Hh + h4) = r;
}

// Layer-0 fix-up: compute final h and emit split bf16 A-operand [hi | lo | hi]
__global__ __launch_bounds__(256) void scan_fix_bf16_kernel(
    const float* __restrict__ cumP, const float* __restrict__ localh,
    __nv_bfloat16* __restrict__ outA)
{
    const int g = blockIdx.x * blockDim.x + threadIdx.x;
    const int h4 = (g & (Hh / 4 - 1)) * 4;
    const int n = g >> 7;
    const int s = n & (Ss - 1);
    const int b = n >> 12;
    const int k = s >> 6;

    float4 P  = *(const float4*)(cumP + (size_t)n * GH + h4);
    float4 hl = *(const float4*)(localh + (size_t)n * Hh + h4);
    float4 e  = *(const float4*)(g_entry + k * NCH + b * Hh + h4);
    float4 r;
    r.x = fmaf(P.x, e.x, hl.x);
    r.y = fmaf(P.y, e.y, hl.y);
    r.z = fmaf(P.z, e.z, hl.z);
    r.w = fmaf(P.w, e.w, hl.w);

    uint32_t h01, h23, l01, l23;
    split4(r, h01, h23, l01, l23);
    __nv_bfloat16* orow = outA + (size_t)n * KP;
    *(uint2*)(orow + h4)        = make_uint2(h01, h23);
    *(uint2*)(orow + 512 + h4)  = make_uint2(l01, l23);
    *(uint2*)(orow + 1024 + h4) = make_uint2(h01, h23);
}

// ===========================================================================
extern "C" void kernel_launch(void* const* d_in, const int* in_sizes, int n_in,
                              void* d_out, int out_size)
{
    const float* x  = (const float*)d_in[0];
    const float* w0 = (const float*)d_in[1];
    const float* b0 = (const float*)d_in[2];
    const float* w1 = (const float*)d_in[3];
    const float* b1 = (const float*)d_in[4];
    float* out = (float*)d_out;

    float* gh;   cudaGetSymbolAddress((void**)&gh,   g_gh);
    float* out0; cudaGetSymbolAddress((void**)&out0, g_out0);
    __nv_bfloat16* Ax;  cudaGetSymbolAddress((void**)&Ax,  g_Ax);
    __nv_bfloat16* A1;  cudaGetSymbolAddress((void**)&A1,  g_A1);
    __nv_bfloat16* Wb0; cudaGetSymbolAddress((void**)&Wb0, g_Wb0);
    __nv_bfloat16* Wb1; cudaGetSymbolAddress((void**)&Wb1, g_Wb1);

    float* nh0 = out + (size_t)Mm * Hh;
    float* nh1 = nh0 + (size_t)Bb * Hh;

    cudaFuncSetAttribute(hmma_gemm_bias,
                         cudaFuncAttributeMaxDynamicSharedMemorySize, GEMM_SMEM);

    dim3 ggrid(GH / BN, Mm / BM);                  // (8, 256)
    const int scan1_blocks = (NCHUNK * NCH) / 256; // 1024
    const int fix_blocks = (Mm * Hh / 4) / 256;    // 16384

    // One-time conversions (cheap)
    conv_b_kernel<<<(GH * 128) / 256, 256>>>(w0, Wb0);
    conv_b_kernel<<<(GH * 128) / 256, 256>>>(w1, Wb1);
    conv_a_kernel<<<(Mm * 128) / 256, 256>>>(x, Ax);

    // ---- Layer 0 ----
    hmma_gemm_bias<<<ggrid, 256, GEMM_SMEM>>>(Ax, Wb0, b0, gh);
    scan_local_kernel<<<scan1_blocks, 256>>>(gh, out0);
    scan_carry_kernel<<<NCH / 256, 256>>>(nh0);
    scan_fix_bf16_kernel<<<fix_blocks, 256>>>(gh, out0, A1);

    // ---- Layer 1 ----
    hmma_gemm_bias<<<ggrid, 256, GEMM_SMEM>>>(A1, Wb1, b1, gh);
    scan_local_kernel<<<scan1_blocks, 256>>>(gh, out);
    scan_carry_kernel<<<NCH / 256, 256>>>(nh1);
    scan_fix_kernel<<<fix_blocks, 256>>>(gh, out);
}

// round 7
// speedup vs baseline: 3.3441x; 1.1944x over previous
#include <cuda_runtime.h>
#include <cuda_fp16.h>
#include <cstdint>
#include <math.h>

// Problem dims (fixed by setup_inputs)
#define Bb 8
#define Ss 4096
#define Dd 512
#define Hh 512
#define GH 1024
#define Mm (Bb * Ss)          // 32768 rows
#define KA 512                // A operand K (plain fp16)
#define KB 1024               // B operand K ([hi | lo] fp16 split)
#define KP 1024               // GEMM K'
#define NCHUNK 64
#define CLEN (Ss / NCHUNK)
#define NCH (Bb * Hh)

// Scratch (device globals: allocation-free per harness rules)
__device__ float g_gh[(size_t)Mm * GH];
__device__ __half g_Ax[(size_t)Mm * KA];    // layer-0 A operand (fp16)
__device__ __half g_A1[(size_t)Mm * KA];    // layer-1 A operand (fp16 h)
__device__ __half g_Wb0[(size_t)GH * KB];   // [hi | lo]
__device__ __half g_Wb1[(size_t)GH * KB];
__device__ float g_carryP[NCHUNK * NCH];
__device__ float g_carryH[NCHUNK * NCH];
__device__ float g_entry[NCHUNK * NCH];

// ===========================================================================
// Helpers
// ===========================================================================
__device__ __forceinline__ uint32_t smem_u32(const void* p) {
    uint32_t a;
    asm("{ .reg .u64 t; cvta.to.shared.u64 t, %1; cvt.u32.u64 %0, t; }" : "=r"(a) : "l"(p));
    return a;
}

#define CP_ASYNC16(smaddr, gptr) \
    asm volatile("cp.async.cg.shared.global [%0], [%1], 16;" :: "r"(smaddr), "l"(gptr) : "memory")
#define CP_COMMIT  asm volatile("cp.async.commit_group;" ::: "memory")
#define CP_WAIT0   asm volatile("cp.async.wait_group 0;" ::: "memory")
#define CP_WAIT1   asm volatile("cp.async.wait_group 1;" ::: "memory")

#define LDSM_X4(r0, r1, r2, r3, addr) \
    asm volatile("ldmatrix.sync.aligned.m8n8.x4.shared.b16 {%0,%1,%2,%3}, [%4];" \
        : "=r"(r0), "=r"(r1), "=r"(r2), "=r"(r3) : "r"(addr))

#define MMA16816(c, a, b) \
    asm volatile("mma.sync.aligned.m16n8k16.row.col.f32.f16.f16.f32 " \
        "{%0,%1,%2,%3}, {%4,%5,%6,%7}, {%8,%9}, {%0,%1,%2,%3};" \
        : "+f"((c)[0]), "+f"((c)[1]), "+f"((c)[2]), "+f"((c)[3]) \
        : "r"((a)[0]), "r"((a)[1]), "r"((a)[2]), "r"((a)[3]), "r"((b)[0]), "r"((b)[1]))

// ===========================================================================
// Conversion kernels
// ===========================================================================
// A: fp32 [rows][512] -> plain fp16 [rows][512]
__global__ __launch_bounds__(256) void conv_a_kernel(
    const float* __restrict__ in, __half* __restrict__ out)
{
    const int g = blockIdx.x * 256 + threadIdx.x;
    const int row = g >> 7;
    const int k4 = (g & 127) * 4;
    float4 f = *(const float4*)(in + (size_t)row * KA + k4);
    __half2 p0 = __floats2half2_rn(f.x, f.y);
    __half2 p1 = __floats2half2_rn(f.z, f.w);
    uint2 v = make_uint2(*reinterpret_cast<uint32_t*>(&p0), *reinterpret_cast<uint32_t*>(&p1));
    *(uint2*)(out + (size_t)row * KA + k4) = v;
}

// B: fp32 [rows][512] -> fp16 [rows][1024] as [hi(512) | lo(512)]
__global__ __launch_bounds__(256) void conv_b_kernel(
    const float* __restrict__ in, __half* __restrict__ out)
{
    const int g = blockIdx.x * 256 + threadIdx.x;
    const int row = g >> 7;
    const int k4 = (g & 127) * 4;
    float4 f = *(const float4*)(in + (size_t)row * KA + k4);
    __half hx = __float2half_rn(f.x), hy = __float2half_rn(f.y);
    __half hz = __float2half_rn(f.z), hw = __float2half_rn(f.w);
    __half2 h0; h0.x = hx; h0.y = hy;
    __half2 h1; h1.x = hz; h1.y = hw;
    __half2 l0 = __floats2half2_rn(f.x - __half2float(hx), f.y - __half2float(hy));
    __half2 l1 = __floats2half2_rn(f.z - __half2float(hz), f.w - __half2float(hw));
    __half* orow = out + (size_t)row * KB;
    *(uint2*)(orow + k4) = make_uint2(*reinterpret_cast<uint32_t*>(&h0),
                                      *reinterpret_cast<uint32_t*>(&h1));
    *(uint2*)(orow + 512 + k4) = make_uint2(*reinterpret_cast<uint32_t*>(&l0),
                                            *reinterpret_cast<uint32_t*>(&l1));
}

// ===========================================================================
// HMMA GEMM with bias: C[m,n] = sum_k A[m,k]*B[n,k'] + bias[n]
// A: [Mm][512] fp16 (reused for k' and k'+512), B: [GH][1024] fp16 [hi|lo]
// CTA tile 128x128, BK=64, 256 threads, 3-stage cp.async pipeline.
// ===========================================================================
#define BM 128
#define BN 128
#define BK 64
#define NKT (KP / BK)          // 16
#define STG 16384
#define GEMM_SMEM (3 * 2 * STG)   // 98304: 3 stages x (16KB A + 16KB B)

__global__ __launch_bounds__(256, 2) void hmma_gemm_bias(
    const __half* __restrict__ A, const __half* __restrict__ Bw,
    const float* __restrict__ bias, float* __restrict__ C)
{
    extern __shared__ char sm[];
    const uint32_t sA = smem_u32(sm);          // [3][16384]
    const uint32_t sB = sA + 3 * STG;          // [3][16384]
    const int tid = threadIdx.x;
    const int lane = tid & 31;
    const int wid = tid >> 5;
    const int rowBase = blockIdx.y * BM;
    const int colBase = blockIdx.x * BN;
    const int wm = (wid & 3) * 32;
    const int wn = (wid >> 2) * 64;

    float acc[2][8][4];
#pragma unroll
    for (int mf = 0; mf < 2; mf++)
#pragma unroll
        for (int nf = 0; nf < 8; nf++)
#pragma unroll
            for (int j = 0; j < 4; j++) acc[mf][nf][j] = 0.f;

    // stage loader: A tile from k-segment (kt&7), B tile from kt. 16KB each.
    auto loadStage = [&](int kt, int s) {
        const int ktA = kt & 7;
#pragma unroll
        for (int i = 0; i < 4; i++) {
            const int id = tid + i * 256;
            const int r = id >> 3, c = id & 7;
            uint32_t off = (uint32_t)(r * 128 + c * 16);
            off ^= (off >> 3) & 0x70;
            CP_ASYNC16(sA + s * STG + off,
                       A + (size_t)(rowBase + r) * KA + ktA * BK + c * 8);
        }
#pragma unroll
        for (int i = 0; i < 4; i++) {
            const int id = tid + i * 256;
            const int r = id >> 3, c = id & 7;
            uint32_t off = (uint32_t)(r * 128 + c * 16);
            off ^= (off >> 3) & 0x70;
            CP_ASYNC16(sB + s * STG + off,
                       Bw + (size_t)(colBase + r) * KB + kt * BK + c * 8);
        }
        CP_COMMIT;
    };

    loadStage(0, 0);
    loadStage(1, 1);

    for (int kt = 0; kt < NKT; kt++) {
        const int s = kt % 3;
        if (kt + 1 < NKT) { CP_WAIT1; } else { CP_WAIT0; }
        __syncthreads();
        if (kt + 2 < NKT) loadStage(kt + 2, (kt + 2) % 3);

        const uint32_t aB = sA + s * STG;
        const uint32_t bB = sB + s * STG;
#pragma unroll
        for (int ks = 0; ks < 4; ks++) {
            uint32_t af[2][4];
#pragma unroll
            for (int mf = 0; mf < 2; mf++) {
                const int r = wm + mf * 16 + (lane & 15);
                const int kb = ks * 32 + (lane >> 4) * 16;
                uint32_t off = (uint32_t)(r * 128 + kb);
                off ^= (off >> 3) & 0x70;
                LDSM_X4(af[mf][0], af[mf][1], af[mf][2], af[mf][3], aB + off);
            }
            uint32_t bf[8][2];
#pragma unroll
            for (int n2 = 0; n2 < 4; n2++) {
                const int r = wn + n2 * 16 + (lane & 7) + ((lane >> 4) & 1) * 8;
                const int kb = ks * 32 + ((lane >> 3) & 1) * 16;
                uint32_t off = (uint32_t)(r * 128 + kb);
                off ^= (off >> 3) & 0x70;
                LDSM_X4(bf[2 * n2][0], bf[2 * n2][1], bf[2 * n2 + 1][0], bf[2 * n2 + 1][1],
                        bB + off);
            }
#pragma unroll
            for (int mf = 0; mf < 2; mf++)
#pragma unroll
                for (int nf = 0; nf < 8; nf++)
                    MMA16816(acc[mf][nf], af[mf], bf[nf]);
        }
        __syncthreads();
    }

    // Epilogue: C = acc + bias
#pragma unroll
    for (int mf = 0; mf < 2; mf++) {
        const int r0 = rowBase + wm + mf * 16 + (lane >> 2);
#pragma unroll
        for (int nf = 0; nf < 8; nf++) {
            const int col = colBase + wn + nf * 8 + 2 * (lane & 3);
            const float bx = __ldg(bias + col);
            const float by = __ldg(bias + col + 1);
            float2 v0, v1;
            v0.x = acc[mf][nf][0] + bx; v0.y = acc[mf][nf][1] + by;
            v1.x = acc[mf][nf][2] + bx; v1.y = acc[mf][nf][3] + by;
            *(float2*)(C + (size_t)r0 * GH + col) = v0;
            *(float2*)(C + (size_t)(r0 + 8) * GH + col) = v1;
        }
    }
}

// ===========================================================================
// Scan: recompute formulation.
// Pass 1: per (chunk, channel) compute carry (P, H) only; gh read-only.
// Pass 2: tiny sequential carry scan -> entry h per chunk + next_hidden.
// Pass 3: re-run recurrence seeded with entry, write final h directly.
// ===========================================================================
__device__ __forceinline__ void step_cv(float gate, float hid, float& z, float& cc, float& gg) {
    z = 1.0f / (1.0f + __expf(-gate));     // sigmoid(gate)
    cc = 1.0f - z;                          // sigmoid(-gate)
    gg = (hid >= 0.0f) ? (hid + 0.5f) : 1.0f / (1.0f + __expf(-hid));
}

__global__ __launch_bounds__(256) void scan_carry1_kernel(const float* __restrict__ gh)
{
    const int g = blockIdx.x * blockDim.x + threadIdx.x;
    const int h = g & (Hh - 1);
    const int rest = g >> 9;
    const int b = rest & (Bb - 1);
    const int k = rest >> 3;

    float P = 1.0f, hl = 0.0f;
    size_t base = ((size_t)(b * Ss + k * CLEN)) * GH + h;
#pragma unroll 4
    for (int i = 0; i < CLEN; i++) {
        float gate = gh[base];
        float hid  = gh[base + Hh];
        float z, cc, gg;
        step_cv(gate, hid, z, cc, gg);
        hl = fmaf(cc, hl, z * gg);
        P *= cc;
        base += GH;
    }
    const int ch = b * Hh + h;
    g_carryP[k * NCH + ch] = P;
    g_carryH[k * NCH + ch] = hl;
}

__global__ __launch_bounds__(256) void scan_carry_kernel(float* __restrict__ nh_out)
{
    const int ch = blockIdx.x * blockDim.x + threadIdx.x;
    float hcur = 0.5f;
#pragma unroll 4
    for (int k = 0; k < NCHUNK; k++) {
        g_entry[k * NCH + ch] = hcur;
        hcur = fmaf(g_carryP[k * NCH + ch], hcur, g_carryH[k * NCH + ch]);
    }
    nh_out[ch] = hcur;
}

// Pass 3, layer-1: write final fp32 output
__global__ __launch_bounds__(256) void scan_emit_f32_kernel(
    const float* __restrict__ gh, float* __restrict__ outbuf)
{
    const int g = blockIdx.x * blockDim.x + threadIdx.x;
    const int h = g & (Hh - 1);
    const int rest = g >> 9;
    const int b = rest & (Bb - 1);
    const int k = rest >> 3;

    float hv = g_entry[k * NCH + b * Hh + h];
    size_t base = ((size_t)(b * Ss + k * CLEN)) * GH + h;
    size_t obase = ((size_t)(b * Ss + k * CLEN)) * Hh + h;
#pragma unroll 4
    for (int i = 0; i < CLEN; i++) {
        float gate = gh[base];
        float hid  = gh[base + Hh];
        float z, cc, gg;
        step_cv(gate, hid, z, cc, gg);
        hv = fmaf(cc, hv, z * gg);
        outbuf[obase] = hv;
        base += GH;
        obase += Hh;
    }
}

// Pass 3, layer-0: write fp16 A operand for layer 1
__global__ __launch_bounds__(256) void scan_emit_f16_kernel(
    const float* __restrict__ gh, __half* __restrict__ outA)
{
    const int g = blockIdx.x * blockDim.x + threadIdx.x;
    const int h = g & (Hh - 1);
    const int rest = g >> 9;
    const int b = rest & (Bb - 1);
    const int k = rest >> 3;

    float hv = g_entry[k * NCH + b * Hh + h];
    size_t base = ((size_t)(b * Ss + k * CLEN)) * GH + h;
    size_t obase = ((size_t)(b * Ss + k * CLEN)) * Hh + h;
#pragma unroll 4
    for (int i = 0; i < CLEN; i++) {
        float gate = gh[base];
        float hid  = gh[base + Hh];
        float z, cc, gg;
        step_cv(gate, hid, z, cc, gg);
        hv = fmaf(cc, hv, z * gg);
        outA[obase] = __float2half_rn(hv);
        base += GH;
        obase += Hh;
    }
}

// ===========================================================================
extern "C" void kernel_launch(void* const* d_in, const int* in_sizes, int n_in,
                              void* d_out, int out_size)
{
    const float* x  = (const float*)d_in[0];
    const float* w0 = (const float*)d_in[1];
    const float* b0 = (const float*)d_in[2];
    const float* w1 = (const float*)d_in[3];
    const float* b1 = (const float*)d_in[4];
    float* out = (float*)d_out;

    float* gh;   cudaGetSymbolAddress((void**)&gh,   g_gh);
    __half* Ax;  cudaGetSymbolAddress((void**)&Ax,  g_Ax);
    __half* A1;  cudaGetSymbolAddress((void**)&A1,  g_A1);
    __half* Wb0; cudaGetSymbolAddress((void**)&Wb0, g_Wb0);
    __half* Wb1; cudaGetSymbolAddress((void**)&Wb1, g_Wb1);

    float* nh0 = out + (size_t)Mm * Hh;
    float* nh1 = nh0 + (size_t)Bb * Hh;

    cudaFuncSetAttribute(hmma_gemm_bias,
                         cudaFuncAttributeMaxDynamicSharedMemorySize, GEMM_SMEM);

    dim3 ggrid(GH / BN, Mm / BM);                  // (8, 256)
    const int scan_blocks = (NCHUNK * NCH) / 256;  // 1024

    // One-time conversions (cheap)
    conv_b_kernel<<<(GH * 128) / 256, 256>>>(w0, Wb0);
    conv_b_kernel<<<(GH * 128) / 256, 256>>>(w1, Wb1);
    conv_a_kernel<<<(Mm * 128) / 256, 256>>>(x, Ax);

    // ---- Layer 0 ----
    hmma_gemm_bias<<<ggrid, 256, GEMM_SMEM>>>(Ax, Wb0, b0, gh);
    scan_carry1_kernel<<<scan_blocks, 256>>>(gh);
    scan_carry_kernel<<<NCH / 256, 256>>>(nh0);
    scan_emit_f16_kernel<<<scan_blocks, 256>>>(gh, A1);

    // ---- Layer 1 ----
    hmma_gemm_bias<<<ggrid, 256, GEMM_SMEM>>>(A1, Wb1, b1, gh);
    scan_carry1_kernel<<<scan_blocks, 256>>>(gh);
    scan_carry_kernel<<<NCH / 256, 256>>>(nh1);
    scan_emit_f32_kernel<<<scan_blocks, 256>>>(gh, out);
}

// round 9
// speedup vs baseline: 3.9541x; 1.1824x over previous
#include <cuda_runtime.h>
#include <cuda_fp16.h>
#include <cstdint>
#include <math.h>

// Problem dims (fixed by setup_inputs)
#define Bb 8
#define Ss 4096
#define Dd 512
#define Hh 512
#define GH 1024
#define Mm (Bb * Ss)          // 32768 rows
#define KA 512                // A operand K (plain fp16)
#define KB 1024               // B operand K ([hi | lo] fp16 split)
#define KP 1024               // GEMM K'
#define NCHUNK 64
#define CLEN (Ss / NCHUNK)
#define NCH (Bb * Hh)

// Scratch (device globals: allocation-free per harness rules)
__device__ float g_gh[(size_t)Mm * GH];     // holds (c,v) float2 pairs after GEMM
__device__ __half g_Ax[(size_t)Mm * KA];    // layer-0 A operand (fp16)
__device__ __half g_A1[(size_t)Mm * KA];    // layer-1 A operand (fp16 h)
__device__ __half g_Wb0[(size_t)GH * KB];   // [hi | lo], rows channel-interleaved
__device__ __half g_Wb1[(size_t)GH * KB];
__device__ float g_carryP[NCHUNK * NCH];
__device__ float g_carryH[NCHUNK * NCH];
__device__ float g_entry[NCHUNK * NCH];

// ===========================================================================
// Helpers
// ===========================================================================
__device__ __forceinline__ uint32_t smem_u32(const void* p) {
    uint32_t a;
    asm("{ .reg .u64 t; cvta.to.shared.u64 t, %1; cvt.u32.u64 %0, t; }" : "=r"(a) : "l"(p));
    return a;
}

#define CP_ASYNC16(smaddr, gptr) \
    asm volatile("cp.async.cg.shared.global [%0], [%1], 16;" :: "r"(smaddr), "l"(gptr) : "memory")
#define CP_COMMIT  asm volatile("cp.async.commit_group;" ::: "memory")
#define CP_WAIT0   asm volatile("cp.async.wait_group 0;" ::: "memory")
#define CP_WAIT1   asm volatile("cp.async.wait_group 1;" ::: "memory")

#define LDSM_X4(r0, r1, r2, r3, addr) \
    asm volatile("ldmatrix.sync.aligned.m8n8.x4.shared.b16 {%0,%1,%2,%3}, [%4];" \
        : "=r"(r0), "=r"(r1), "=r"(r2), "=r"(r3) : "r"(addr))

#define MMA16816(c, a, b) \
    asm volatile("mma.sync.aligned.m16n8k16.row.col.f32.f16.f16.f32 " \
        "{%0,%1,%2,%3}, {%4,%5,%6,%7}, {%8,%9}, {%0,%1,%2,%3};" \
        : "+f"((c)[0]), "+f"((c)[1]), "+f"((c)[2]), "+f"((c)[3]) \
        : "r"((a)[0]), "r"((a)[1]), "r"((a)[2]), "r"((a)[3]), "r"((b)[0]), "r"((b)[1]))

// Fused activation: from (gate, hidden) produce (c, v)
//   c = sigmoid(-gate), v = sigmoid(gate) * g(hidden)
__device__ __forceinline__ float2 act_pair(float gate, float hid) {
    float e = __expf(-gate);
    float z = __fdividef(1.0f, 1.0f + e);    // sigmoid(gate)
    float cc = e * z;                         // sigmoid(-gate)
    float gg = (hid >= 0.0f) ? (hid + 0.5f)
                             : __fdividef(1.0f, 1.0f + __expf(-hid));
    float2 r; r.x = cc; r.y = z * gg;
    return r;
}

// ===========================================================================
// Conversion kernels
// ===========================================================================
// A: fp32 [rows][512] -> plain fp16 [rows][512]
__global__ __launch_bounds__(256) void conv_a_kernel(
    const float* __restrict__ in, __half* __restrict__ out)
{
    const int g = blockIdx.x * 256 + threadIdx.x;
    const int row = g >> 7;
    const int k4 = (g & 127) * 4;
    float4 f = *(const float4*)(in + (size_t)row * KA + k4);
    __half2 p0 = __floats2half2_rn(f.x, f.y);
    __half2 p1 = __floats2half2_rn(f.z, f.w);
    uint2 v = make_uint2(*reinterpret_cast<uint32_t*>(&p0), *reinterpret_cast<uint32_t*>(&p1));
    *(uint2*)(out + (size_t)row * KA + k4) = v;
}

// B: fp32 [rows][512] -> fp16 [rows][1024] as [hi(512) | lo(512)],
// with output-channel interleave: source row n -> dest row (2n) for n<512
// (gate), (2(n-512)+1) for n>=512 (hidden). So GEMM col 2h=gate_h, 2h+1=hid_h.
__global__ __launch_bounds__(256) void conv_b_kernel(
    const float* __restrict__ in, __half* __restrict__ out)
{
    const int g = blockIdx.x * 256 + threadIdx.x;
    const int row = g >> 7;
    const int prow = (row < 512) ? (row * 2) : ((row - 512) * 2 + 1);
    const int k4 = (g & 127) * 4;
    float4 f = *(const float4*)(in + (size_t)row * KA + k4);
    __half hx = __float2half_rn(f.x), hy = __float2half_rn(f.y);
    __half hz = __float2half_rn(f.z), hw = __float2half_rn(f.w);
    __half2 h0; h0.x = hx; h0.y = hy;
    __half2 h1; h1.x = hz; h1.y = hw;
    __half2 l0 = __floats2half2_rn(f.x - __half2float(hx), f.y - __half2float(hy));
    __half2 l1 = __floats2half2_rn(f.z - __half2float(hz), f.w - __half2float(hw));
    __half* orow = out + (size_t)prow * KB;
    *(uint2*)(orow + k4) = make_uint2(*reinterpret_cast<uint32_t*>(&h0),
                                      *reinterpret_cast<uint32_t*>(&h1));
    *(uint2*)(orow + 512 + k4) = make_uint2(*reinterpret_cast<uint32_t*>(&l0),
                                            *reinterpret_cast<uint32_t*>(&l1));
}

// ===========================================================================
// HMMA GEMM + fused activation.
// C'[m, 2h..2h+1] = (c, v) computed from (gate, hidden) = GEMM + bias.
// A: [Mm][512] fp16, B: [GH][1024] fp16 [hi|lo] channel-interleaved rows.
// CTA tile 128x128, BK=64, 256 threads, 3-stage cp.async, ONE sync/K-tile.
// ===========================================================================
#define BM 128
#define BN 128
#define BK 64
#define NKT (KP / BK)          // 16
#define STG 16384
#define GEMM_SMEM (3 * 2 * STG)   // 98304

__global__ __launch_bounds__(256, 2) void hmma_gemm_act(
    const __half* __restrict__ A, const __half* __restrict__ Bw,
    const float* __restrict__ bias, float* __restrict__ C)
{
    extern __shared__ char sm[];
    const uint32_t sA = smem_u32(sm);          // [3][16384]
    const uint32_t sB = sA + 3 * STG;          // [3][16384]
    const int tid = threadIdx.x;
    const int lane = tid & 31;
    const int wid = tid >> 5;
    const int rowBase = blockIdx.y * BM;
    const int colBase = blockIdx.x * BN;
    const int wm = (wid & 3) * 32;
    const int wn = (wid >> 2) * 64;

    float acc[2][8][4];
#pragma unroll
    for (int mf = 0; mf < 2; mf++)
#pragma unroll
        for (int nf = 0; nf < 8; nf++)
#pragma unroll
            for (int j = 0; j < 4; j++) acc[mf][nf][j] = 0.f;

    auto loadStage = [&](int kt, int s) {
        const int ktA = kt & 7;
#pragma unroll
        for (int i = 0; i < 4; i++) {
            const int id = tid + i * 256;
            const int r = id >> 3, c = id & 7;
            uint32_t off = (uint32_t)(r * 128 + c * 16);
            off ^= (off >> 3) & 0x70;
            CP_ASYNC16(sA + s * STG + off,
                       A + (size_t)(rowBase + r) * KA + ktA * BK + c * 8);
        }
#pragma unroll
        for (int i = 0; i < 4; i++) {
            const int id = tid + i * 256;
            const int r = id >> 3, c = id & 7;
            uint32_t off = (uint32_t)(r * 128 + c * 16);
            off ^= (off >> 3) & 0x70;
            CP_ASYNC16(sB + s * STG + off,
                       Bw + (size_t)(colBase + r) * KB + kt * BK + c * 8);
        }
        CP_COMMIT;
    };

    loadStage(0, 0);
    loadStage(1, 1);

    for (int kt = 0; kt < NKT; kt++) {
        const int s = kt % 3;
        if (kt + 1 < NKT) { CP_WAIT1; } else { CP_WAIT0; }
        __syncthreads();   // single barrier per K-tile: protects stage reuse
        if (kt + 2 < NKT) loadStage(kt + 2, (kt + 2) % 3);

        const uint32_t aB = sA + s * STG;
        const uint32_t bB = sB + s * STG;
#pragma unroll
        for (int ks = 0; ks < 4; ks++) {
            uint32_t af[2][4];
#pragma unroll
            for (int mf = 0; mf < 2; mf++) {
                const int r = wm + mf * 16 + (lane & 15);
                const int kb = ks * 32 + (lane >> 4) * 16;
                uint32_t off = (uint32_t)(r * 128 + kb);
                off ^= (off >> 3) & 0x70;
                LDSM_X4(af[mf][0], af[mf][1], af[mf][2], af[mf][3], aB + off);
            }
            uint32_t bf[8][2];
#pragma unroll
            for (int n2 = 0; n2 < 4; n2++) {
                const int r = wn + n2 * 16 + (lane & 7) + ((lane >> 4) & 1) * 8;
                const int kb = ks * 32 + ((lane >> 3) & 1) * 16;
                uint32_t off = (uint32_t)(r * 128 + kb);
                off ^= (off >> 3) & 0x70;
                LDSM_X4(bf[2 * n2][0], bf[2 * n2][1], bf[2 * n2 + 1][0], bf[2 * n2 + 1][1],
                        bB + off);
            }
#pragma unroll
            for (int mf = 0; mf < 2; mf++)
#pragma unroll
                for (int nf = 0; nf < 8; nf++)
                    MMA16816(acc[mf][nf], af[mf], bf[nf]);
        }
    }

    // Epilogue: each float2 pair = (gate, hidden) of channel h -> store (c, v)
#pragma unroll
    for (int nf = 0; nf < 8; nf++) {
        const int col = colBase + wn + nf * 8 + 2 * (lane & 3);   // even
        const int h = col >> 1;
        const float bg = __ldg(bias + h);
        const float bh = __ldg(bias + 512 + h);
#pragma unroll
        for (int mf = 0; mf < 2; mf++) {
            const int r0 = rowBase + wm + mf * 16 + (lane >> 2);
            float2 p0 = act_pair(acc[mf][nf][0] + bg, acc[mf][nf][1] + bh);
            float2 p1 = act_pair(acc[mf][nf][2] + bg, acc[mf][nf][3] + bh);
            *(float2*)(C + (size_t)r0 * GH + col) = p0;
            *(float2*)(C + (size_t)(r0 + 8) * GH + col) = p1;
        }
    }
}

// ===========================================================================
// Scan over (c, v) pairs: h_t = c_t * h_{t-1} + v_t
// Pass 1: per-chunk carries. Pass 2: tiny carry scan. Pass 3: emit (recompute).
// ===========================================================================
__global__ __launch_bounds__(256) void scan_carry1_kernel(const float* __restrict__ gh)
{
    const int g = blockIdx.x * blockDim.x + threadIdx.x;
    const int h = g & (Hh - 1);
    const int rest = g >> 9;
    const int b = rest & (Bb - 1);
    const int k = rest >> 3;

    const float2* p = (const float2*)gh + ((size_t)(b * Ss + k * CLEN) * Hh + h);
    float P = 1.0f, hl = 0.0f;
#pragma unroll 8
    for (int i = 0; i < CLEN; i++) {
        float2 cv = *p;
        hl = fmaf(cv.x, hl, cv.y);
        P *= cv.x;
        p += Hh;
    }
    const int ch = b * Hh + h;
    g_carryP[k * NCH + ch] = P;
    g_carryH[k * NCH + ch] = hl;
}

__global__ __launch_bounds__(256) void scan_carry_kernel(float* __restrict__ nh_out)
{
    const int ch = blockIdx.x * blockDim.x + threadIdx.x;
    float hcur = 0.5f;
#pragma unroll 4
    for (int k = 0; k < NCHUNK; k++) {
        g_entry[k * NCH + ch] = hcur;
        hcur = fmaf(g_carryP[k * NCH + ch], hcur, g_carryH[k * NCH + ch]);
    }
    nh_out[ch] = hcur;
}

// Pass 3, layer-1: write final fp32 output
__global__ __launch_bounds__(256) void scan_emit_f32_kernel(
    const float* __restrict__ gh, float* __restrict__ outbuf)
{
    const int g = blockIdx.x * blockDim.x + threadIdx.x;
    const int h = g & (Hh - 1);
    const int rest = g >> 9;
    const int b = rest & (Bb - 1);
    const int k = rest >> 3;

    float hv = g_entry[k * NCH + b * Hh + h];
    const float2* p = (const float2*)gh + ((size_t)(b * Ss + k * CLEN) * Hh + h);
    size_t obase = ((size_t)(b * Ss + k * CLEN)) * Hh + h;
#pragma unroll 8
    for (int i = 0; i < CLEN; i++) {
        float2 cv = *p;
        hv = fmaf(cv.x, hv, cv.y);
        outbuf[obase] = hv;
        p += Hh;
        obase += Hh;
    }
}

// Pass 3, layer-0: write fp16 A operand for layer 1
__global__ __launch_bounds__(256) void scan_emit_f16_kernel(
    const float* __restrict__ gh, __half* __restrict__ outA)
{
    const int g = blockIdx.x * blockDim.x + threadIdx.x;
    const int h = g & (Hh - 1);
    const int rest = g >> 9;
    const int b = rest & (Bb - 1);
    const int k = rest >> 3;

    float hv = g_entry[k * NCH + b * Hh + h];
    const float2* p = (const float2*)gh + ((size_t)(b * Ss + k * CLEN) * Hh + h);
    size_t obase = ((size_t)(b * Ss + k * CLEN)) * Hh + h;
#pragma unroll 8
    for (int i = 0; i < CLEN; i++) {
        float2 cv = *p;
        hv = fmaf(cv.x, hv, cv.y);
        outA[obase] = __float2half_rn(hv);
        p += Hh;
        obase += Hh;
    }
}

// ===========================================================================
extern "C" void kernel_launch(void* const* d_in, const int* in_sizes, int n_in,
                              void* d_out, int out_size)
{
    const float* x  = (const float*)d_in[0];
    const float* w0 = (const float*)d_in[1];
    const float* b0 = (const float*)d_in[2];
    const float* w1 = (const float*)d_in[3];
    const float* b1 = (const float*)d_in[4];
    float* out = (float*)d_out;

    float* gh;   cudaGetSymbolAddress((void**)&gh,   g_gh);
    __half* Ax;  cudaGetSymbolAddress((void**)&Ax,  g_Ax);
    __half* A1;  cudaGetSymbolAddress((void**)&A1,  g_A1);
    __half* Wb0; cudaGetSymbolAddress((void**)&Wb0, g_Wb0);
    __half* Wb1; cudaGetSymbolAddress((void**)&Wb1, g_Wb1);

    float* nh0 = out + (size_t)Mm * Hh;
    float* nh1 = nh0 + (size_t)Bb * Hh;

    cudaFuncSetAttribute(hmma_gemm_act,
                         cudaFuncAttributeMaxDynamicSharedMemorySize, GEMM_SMEM);

    dim3 ggrid(GH / BN, Mm / BM);                  // (8, 256)
    const int scan_blocks = (NCHUNK * NCH) / 256;  // 1024

    // One-time conversions (cheap)
    conv_b_kernel<<<(GH * 128) / 256, 256>>>(w0, Wb0);
    conv_b_kernel<<<(GH * 128) / 256, 256>>>(w1, Wb1);
    conv_a_kernel<<<(Mm * 128) / 256, 256>>>(x, Ax);

    // ---- Layer 0 ----
    hmma_gemm_act<<<ggrid, 256, GEMM_SMEM>>>(Ax, Wb0, b0, gh);
    scan_carry1_kernel<<<scan_blocks, 256>>>(gh);
    scan_carry_kernel<<<NCH / 256, 256>>>(nh0);
    scan_emit_f16_kernel<<<scan_blocks, 256>>>(gh, A1);

    // ---- Layer 1 ----
    hmma_gemm_act<<<ggrid, 256, GEMM_SMEM>>>(A1, Wb1, b1, gh);
    scan_carry1_kernel<<<scan_blocks, 256>>>(gh);
    scan_carry_kernel<<<NCH / 256, 256>>>(nh1);
    scan_emit_f32_kernel<<<scan_blocks, 256>>>(gh, out);
}

// round 10
// speedup vs baseline: 6.2081x; 1.5700x over previous
#include <cuda_runtime.h>
#include <cuda_fp16.h>
#include <cstdint>
#include <math.h>

// Problem dims (fixed by setup_inputs)
#define Bb 8
#define Ss 4096
#define Dd 512
#define Hh 512
#define GH 1024
#define Mm (Bb * Ss)          // 32768 rows
#define KA 512                // A operand K (plain fp16)
#define KB 512                // B operand K (plain fp16)
#define KP 512                // GEMM K'
#define NCHUNK 64
#define CLEN (Ss / NCHUNK)
#define NCH (Bb * Hh)

// Scratch (device globals: allocation-free per harness rules)
__device__ __half g_gh[(size_t)Mm * GH];    // (c,v) half2 pairs after GEMM+act
__device__ __half g_Ax[(size_t)Mm * KA];    // layer-0 A operand (fp16)
__device__ __half g_A1[(size_t)Mm * KA];    // layer-1 A operand (fp16 h)
__device__ __half g_Wb0[(size_t)GH * KB];   // fp16 weights, rows channel-interleaved
__device__ __half g_Wb1[(size_t)GH * KB];
__device__ float g_carryP[NCHUNK * NCH];
__device__ float g_carryH[NCHUNK * NCH];
__device__ float g_entry[NCHUNK * NCH];

// ===========================================================================
// Helpers
// ===========================================================================
__device__ __forceinline__ uint32_t smem_u32(const void* p) {
    uint32_t a;
    asm("{ .reg .u64 t; cvta.to.shared.u64 t, %1; cvt.u32.u64 %0, t; }" : "=r"(a) : "l"(p));
    return a;
}

#define CP_ASYNC16(smaddr, gptr) \
    asm volatile("cp.async.cg.shared.global [%0], [%1], 16;" :: "r"(smaddr), "l"(gptr) : "memory")
#define CP_COMMIT  asm volatile("cp.async.commit_group;" ::: "memory")
#define CP_WAIT0   asm volatile("cp.async.wait_group 0;" ::: "memory")
#define CP_WAIT1   asm volatile("cp.async.wait_group 1;" ::: "memory")

#define LDSM_X4(r0, r1, r2, r3, addr) \
    asm volatile("ldmatrix.sync.aligned.m8n8.x4.shared.b16 {%0,%1,%2,%3}, [%4];" \
        : "=r"(r0), "=r"(r1), "=r"(r2), "=r"(r3) : "r"(addr))

#define MMA16816(c, a, b) \
    asm volatile("mma.sync.aligned.m16n8k16.row.col.f32.f16.f16.f32 " \
        "{%0,%1,%2,%3}, {%4,%5,%6,%7}, {%8,%9}, {%0,%1,%2,%3};" \
        : "+f"((c)[0]), "+f"((c)[1]), "+f"((c)[2]), "+f"((c)[3]) \
        : "r"((a)[0]), "r"((a)[1]), "r"((a)[2]), "r"((a)[3]), "r"((b)[0]), "r"((b)[1]))

// Fused activation: from (gate, hidden) produce (c, v)
//   c = sigmoid(-gate), v = sigmoid(gate) * g(hidden)
__device__ __forceinline__ float2 act_pair(float gate, float hid) {
    float e = __expf(-gate);
    float z = __fdividef(1.0f, 1.0f + e);    // sigmoid(gate)
    float cc = e * z;                         // sigmoid(-gate)
    float gg = (hid >= 0.0f) ? (hid + 0.5f)
                             : __fdividef(1.0f, 1.0f + __expf(-hid));
    float2 r; r.x = cc; r.y = z * gg;
    return r;
}

// ===========================================================================
// Conversion kernels
// ===========================================================================
// A: fp32 [rows][512] -> plain fp16 [rows][512]
__global__ __launch_bounds__(256) void conv_a_kernel(
    const float* __restrict__ in, __half* __restrict__ out)
{
    const int g = blockIdx.x * 256 + threadIdx.x;
    const int row = g >> 7;
    const int k4 = (g & 127) * 4;
    float4 f = *(const float4*)(in + (size_t)row * KA + k4);
    __half2 p0 = __floats2half2_rn(f.x, f.y);
    __half2 p1 = __floats2half2_rn(f.z, f.w);
    uint2 v = make_uint2(*reinterpret_cast<uint32_t*>(&p0), *reinterpret_cast<uint32_t*>(&p1));
    *(uint2*)(out + (size_t)row * KA + k4) = v;
}

// B: fp32 [1024][512] -> fp16 [1024][512] with output-channel interleave:
// source row n -> dest row (2n) for n<512 (gate), (2(n-512)+1) for n>=512
// (hidden). So GEMM col 2h = gate_h, 2h+1 = hid_h.
__global__ __launch_bounds__(256) void conv_b_kernel(
    const float* __restrict__ in, __half* __restrict__ out)
{
    const int g = blockIdx.x * 256 + threadIdx.x;
    const int row = g >> 7;
    const int prow = (row < 512) ? (row * 2) : ((row - 512) * 2 + 1);
    const int k4 = (g & 127) * 4;
    float4 f = *(const float4*)(in + (size_t)row * KA + k4);
    __half2 p0 = __floats2half2_rn(f.x, f.y);
    __half2 p1 = __floats2half2_rn(f.z, f.w);
    uint2 v = make_uint2(*reinterpret_cast<uint32_t*>(&p0), *reinterpret_cast<uint32_t*>(&p1));
    *(uint2*)(out + (size_t)prow * KB + k4) = v;
}

// ===========================================================================
// HMMA GEMM + fused activation, fp16 (c,v) output.
// A: [Mm][512] fp16, B: [GH][512] fp16 channel-interleaved rows.
// CTA tile 128x128, BK=64, 256 threads, 3-stage cp.async, one sync/K-tile.
// ===========================================================================
#define BM 128
#define BN 128
#define BK 64
#define NKT (KP / BK)          // 8
#define STG 16384
#define GEMM_SMEM (3 * 2 * STG)   // 98304

__global__ __launch_bounds__(256, 2) void hmma_gemm_act(
    const __half* __restrict__ A, const __half* __restrict__ Bw,
    const float* __restrict__ bias, __half2* __restrict__ C2)
{
    extern __shared__ char sm[];
    const uint32_t sA = smem_u32(sm);          // [3][16384]
    const uint32_t sB = sA + 3 * STG;          // [3][16384]
    const int tid = threadIdx.x;
    const int lane = tid & 31;
    const int wid = tid >> 5;
    const int rowBase = blockIdx.y * BM;
    const int colBase = blockIdx.x * BN;
    const int wm = (wid & 3) * 32;
    const int wn = (wid >> 2) * 64;

    float acc[2][8][4];
#pragma unroll
    for (int mf = 0; mf < 2; mf++)
#pragma unroll
        for (int nf = 0; nf < 8; nf++)
#pragma unroll
            for (int j = 0; j < 4; j++) acc[mf][nf][j] = 0.f;

    auto loadStage = [&](int kt, int s) {
#pragma unroll
        for (int i = 0; i < 4; i++) {
            const int id = tid + i * 256;
            const int r = id >> 3, c = id & 7;
            uint32_t off = (uint32_t)(r * 128 + c * 16);
            off ^= (off >> 3) & 0x70;
            CP_ASYNC16(sA + s * STG + off,
                       A + (size_t)(rowBase + r) * KA + kt * BK + c * 8);
        }
#pragma unroll
        for (int i = 0; i < 4; i++) {
            const int id = tid + i * 256;
            const int r = id >> 3, c = id & 7;
            uint32_t off = (uint32_t)(r * 128 + c * 16);
            off ^= (off >> 3) & 0x70;
            CP_ASYNC16(sB + s * STG + off,
                       Bw + (size_t)(colBase + r) * KB + kt * BK + c * 8);
        }
        CP_COMMIT;
    };

    loadStage(0, 0);
    loadStage(1, 1);

    for (int kt = 0; kt < NKT; kt++) {
        const int s = kt % 3;
        if (kt + 1 < NKT) { CP_WAIT1; } else { CP_WAIT0; }
        __syncthreads();   // single barrier per K-tile: protects stage reuse
        if (kt + 2 < NKT) loadStage(kt + 2, (kt + 2) % 3);

        const uint32_t aB = sA + s * STG;
        const uint32_t bB = sB + s * STG;
#pragma unroll
        for (int ks = 0; ks < 4; ks++) {
            uint32_t af[2][4];
#pragma unroll
            for (int mf = 0; mf < 2; mf++) {
                const int r = wm + mf * 16 + (lane & 15);
                const int kb = ks * 32 + (lane >> 4) * 16;
                uint32_t off = (uint32_t)(r * 128 + kb);
                off ^= (off >> 3) & 0x70;
                LDSM_X4(af[mf][0], af[mf][1], af[mf][2], af[mf][3], aB + off);
            }
            uint32_t bf[8][2];
#pragma unroll
            for (int n2 = 0; n2 < 4; n2++) {
                const int r = wn + n2 * 16 + (lane & 7) + ((lane >> 4) & 1) * 8;
                const int kb = ks * 32 + ((lane >> 3) & 1) * 16;
                uint32_t off = (uint32_t)(r * 128 + kb);
                off ^= (off >> 3) & 0x70;
                LDSM_X4(bf[2 * n2][0], bf[2 * n2][1], bf[2 * n2 + 1][0], bf[2 * n2 + 1][1],
                        bB + off);
            }
#pragma unroll
            for (int mf = 0; mf < 2; mf++)
#pragma unroll
                for (int nf = 0; nf < 8; nf++)
                    MMA16816(acc[mf][nf], af[mf], bf[nf]);
        }
    }

    // Epilogue: each float2 pair = (gate, hidden) of channel h -> store half2 (c, v)
#pragma unroll
    for (int nf = 0; nf < 8; nf++) {
        const int col = colBase + wn + nf * 8 + 2 * (lane & 3);   // even
        const int h = col >> 1;
        const float bg = __ldg(bias + h);
        const float bh = __ldg(bias + 512 + h);
#pragma unroll
        for (int mf = 0; mf < 2; mf++) {
            const int r0 = rowBase + wm + mf * 16 + (lane >> 2);
            float2 p0 = act_pair(acc[mf][nf][0] + bg, acc[mf][nf][1] + bh);
            float2 p1 = act_pair(acc[mf][nf][2] + bg, acc[mf][nf][3] + bh);
            C2[(size_t)r0 * Hh + h] = __floats2half2_rn(p0.x, p0.y);
            C2[(size_t)(r0 + 8) * Hh + h] = __floats2half2_rn(p1.x, p1.y);
        }
    }
}

// ===========================================================================
// Scan over half2 (c, v) pairs: h_t = c_t * h_{t-1} + v_t   (fp32 state)
// ===========================================================================
__global__ __launch_bounds__(256) void scan_carry1_kernel(const __half2* __restrict__ gh)
{
    const int g = blockIdx.x * blockDim.x + threadIdx.x;
    const int h = g & (Hh - 1);
    const int rest = g >> 9;
    const int b = rest & (Bb - 1);
    const int k = rest >> 3;

    const __half2* p = gh + ((size_t)(b * Ss + k * CLEN) * Hh + h);
    float P = 1.0f, hl = 0.0f;
#pragma unroll 8
    for (int i = 0; i < CLEN; i++) {
        float2 cv = __half22float2(*p);
        hl = fmaf(cv.x, hl, cv.y);
        P *= cv.x;
        p += Hh;
    }
    const int ch = b * Hh + h;
    g_carryP[k * NCH + ch] = P;
    g_carryH[k * NCH + ch] = hl;
}

__global__ __launch_bounds__(256) void scan_carry_kernel(float* __restrict__ nh_out)
{
    const int ch = blockIdx.x * blockDim.x + threadIdx.x;
    float hcur = 0.5f;
#pragma unroll 4
    for (int k = 0; k < NCHUNK; k++) {
        g_entry[k * NCH + ch] = hcur;
        hcur = fmaf(g_carryP[k * NCH + ch], hcur, g_carryH[k * NCH + ch]);
    }
    nh_out[ch] = hcur;
}

// Pass 3, layer-1: write final fp32 output
__global__ __launch_bounds__(256) void scan_emit_f32_kernel(
    const __half2* __restrict__ gh, float* __restrict__ outbuf)
{
    const int g = blockIdx.x * blockDim.x + threadIdx.x;
    const int h = g & (Hh - 1);
    const int rest = g >> 9;
    const int b = rest & (Bb - 1);
    const int k = rest >> 3;

    float hv = g_entry[k * NCH + b * Hh + h];
    const __half2* p = gh + ((size_t)(b * Ss + k * CLEN) * Hh + h);
    size_t obase = ((size_t)(b * Ss + k * CLEN)) * Hh + h;
#pragma unroll 8
    for (int i = 0; i < CLEN; i++) {
        float2 cv = __half22float2(*p);
        hv = fmaf(cv.x, hv, cv.y);
        outbuf[obase] = hv;
        p += Hh;
        obase += Hh;
    }
}

// Pass 3, layer-0: write fp16 A operand for layer 1
__global__ __launch_bounds__(256) void scan_emit_f16_kernel(
    const __half2* __restrict__ gh, __half* __restrict__ outA)
{
    const int g = blockIdx.x * blockDim.x + threadIdx.x;
    const int h = g & (Hh - 1);
    const int rest = g >> 9;
    const int b = rest & (Bb - 1);
    const int k = rest >> 3;

    float hv = g_entry[k * NCH + b * Hh + h];
    const __half2* p = gh + ((size_t)(b * Ss + k * CLEN) * Hh + h);
    size_t obase = ((size_t)(b * Ss + k * CLEN)) * Hh + h;
#pragma unroll 8
    for (int i = 0; i < CLEN; i++) {
        float2 cv = __half22float2(*p);
        hv = fmaf(cv.x, hv, cv.y);
        outA[obase] = __float2half_rn(hv);
        p += Hh;
        obase += Hh;
    }
}

// ===========================================================================
extern "C" void kernel_launch(void* const* d_in, const int* in_sizes, int n_in,
                              void* d_out, int out_size)
{
    const float* x  = (const float*)d_in[0];
    const float* w0 = (const float*)d_in[1];
    const float* b0 = (const float*)d_in[2];
    const float* w1 = (const float*)d_in[3];
    const float* b1 = (const float*)d_in[4];
    float* out = (float*)d_out;

    __half* gh;  cudaGetSymbolAddress((void**)&gh,  g_gh);
    __half* Ax;  cudaGetSymbolAddress((void**)&Ax,  g_Ax);
    __half* A1;  cudaGetSymbolAddress((void**)&A1,  g_A1);
    __half* Wb0; cudaGetSymbolAddress((void**)&Wb0, g_Wb0);
    __half* Wb1; cudaGetSymbolAddress((void**)&Wb1, g_Wb1);

    float* nh0 = out + (size_t)Mm * Hh;
    float* nh1 = nh0 + (size_t)Bb * Hh;

    cudaFuncSetAttribute(hmma_gemm_act,
                         cudaFuncAttributeMaxDynamicSharedMemorySize, GEMM_SMEM);

    dim3 ggrid(GH / BN, Mm / BM);                  // (8, 256)
    const int scan_blocks = (NCHUNK * NCH) / 256;  // 1024

    // One-time conversions (cheap)
    conv_b_kernel<<<(GH * 128) / 256, 256>>>(w0, Wb0);
    conv_b_kernel<<<(GH * 128) / 256, 256>>>(w1, Wb1);
    conv_a_kernel<<<(Mm * 128) / 256, 256>>>(x, Ax);

    // ---- Layer 0 ----
    hmma_gemm_act<<<ggrid, 256, GEMM_SMEM>>>(Ax, Wb0, b0, (__half2*)gh);
    scan_carry1_kernel<<<scan_blocks, 256>>>((const __half2*)gh);
    scan_carry_kernel<<<NCH / 256, 256>>>(nh0);
    scan_emit_f16_kernel<<<scan_blocks, 256>>>((const __half2*)gh, A1);

    // ---- Layer 1 ----
    hmma_gemm_act<<<ggrid, 256, GEMM_SMEM>>>(A1, Wb1, b1, (__half2*)gh);
    scan_carry1_kernel<<<scan_blocks, 256>>>((const __half2*)gh);
    scan_carry_kernel<<<NCH / 256, 256>>>(nh1);
    scan_emit_f32_kernel<<<scan_blocks, 256>>>((const __half2*)gh, out);
}